// round 6
// baseline (speedup 1.0000x reference)
#include <cuda_runtime.h>
#include <cuda_bf16.h>
#include <cstdint>

// KinematicWaveRouting via the scalar transfer function of the 20-segment chain.
//   y_t = y_{t-1} + u_t - sum_{m=20..31} c_m * u_{t-m},  u = runoff * basin * 50
//   c_m renormalized (sum = 1 exactly). Max lag 31 -> full 32-reg prev window.
// One warp owns 2 rows; lane = (row_sel = lane>>4, chunk = lane&15), CHUNK=256,
// warm-started 32 steps early (halo 12.5%). Double-buffered smem transpose
// tile; next group's inputs prefetched with cp.async (no registers, no
// mid-compute scoreboard stalls), waited at the group boundary.

#define T_LEN   4096
#define CHUNK   256
#define NSER    32        // series per warp = 2 rows x 16 chunks
#define WPB     4         // warps per block (8 rows/block)
#define NTAPS   12

// -c_m (renormalized), m = 20..31
static __device__ constexpr float CNEG[NTAPS] = {
    -0.12157942f, -0.24315882f, -0.25531676f, -0.18723229f,
    -0.10765857f, -0.05167612f, -0.02153171f, -0.00799749f,
    -0.00269915f, -0.00083973f, -0.00024352f, -0.00006643f
};
// g_m for m = 20..31 (warm-start FIR weights; g_m = 1 for m <= 19)
static __device__ constexpr float GW[12] = {
    0.878423345f, 0.635270036f, 0.379959062f, 0.192731014f,
    0.085074886f, 0.033399937f, 0.011868715f, 0.003871403f,
    0.001172310f, 0.000332598f, 0.000089080f, 0.000022666f
};

__device__ __forceinline__ void cpasync4(uint32_t s, const float* g) {
    asm volatile("cp.async.ca.shared.global [%0], [%1], 4;" :: "r"(s), "l"(g) : "memory");
}
__device__ __forceinline__ void cpcommit() {
    asm volatile("cp.async.commit_group;" ::: "memory");
}
template <int N>
__device__ __forceinline__ void cpwait() {
    asm volatile("cp.async.wait_group %0;" :: "n"(N) : "memory");
}

// Prefetch group GIDX's inputs (32 coalesced 128B lines) into tile at TU
// (u32 smem base already offset by lane*4). rl0/rl1 include (+lane-32).
#define PREFETCH(TU, GIDX)                                                  \
    do {                                                                    \
        _Pragma("unroll")                                                   \
        for (int c = 0; c < NSER; c++) {                                    \
            const float* gp = ((c < 16) ? rl0 : rl1)                        \
                              + (c & 15) * CHUNK + (GIDX) * 32;             \
            cpasync4((TU) + c * 132, gp);                                   \
        }                                                                   \
        cpcommit();                                                         \
    } while (0)

// One 32-step group: PREV[32]/CUR[32] register windows; outputs overwrite
// the lane's own tile row in place.
#define GROUP_BODY(PREV, CUR, TC)                                           \
    do {                                                                    \
        float* tlrow = &TC[lane][0];                                        \
        _Pragma("unroll")                                                   \
        for (int j2 = 0; j2 < 32; j2++) CUR[j2] = tlrow[j2];                \
        _Pragma("unroll")                                                   \
        for (int m = 0; m < 32; m++) {                                      \
            float acc = CUR[m];                                             \
            _Pragma("unroll")                                               \
            for (int j = 0; j < NTAPS; j++) {                               \
                const int k = m - (20 + j);                                 \
                float w = (k >= 0) ? CUR[k] : PREV[32 + k];                 \
                acc = fmaf(CNEG[j], w, acc);                                \
            }                                                               \
            y += acc;                                                       \
            tlrow[m] = y;                                                   \
        }                                                                   \
    } while (0)

// Coalesced scaled store of group GIDX's outlets.
#define DRAIN(TC, GIDX)                                                     \
    do {                                                                    \
        _Pragma("unroll 8")                                                 \
        for (int c = 0; c < NSER; c++) {                                    \
            float v = TC[c][lane] * ((c < 16) ? s0 : s1);                   \
            ((c < 16) ? ol0 : ol1)[(c & 15) * CHUNK + ((GIDX) - 1) * 32] = v; \
        }                                                                   \
    } while (0)

__global__ __launch_bounds__(128, 6)
void kinematic_wave_kernel(const float* __restrict__ runoff,
                           const float* __restrict__ basin,
                           float* __restrict__ out,
                           int B)
{
    __shared__ float tile[2][WPB][NSER][33];   // stride 33: conflict-free

    const int warp = threadIdx.x >> 5;
    const int lane = threadIdx.x & 31;
    const int row0 = (blockIdx.x * WPB + warp) * 2;
    if (row0 >= B) return;

    float (*T0)[33] = tile[0][warp];
    float (*T1)[33] = tile[1][warp];
    const uint32_t T0u = (uint32_t)__cvta_generic_to_shared(&T0[0][0]) + lane * 4;
    const uint32_t T1u = (uint32_t)__cvta_generic_to_shared(&T1[0][0]) + lane * 4;

    const float s0 = basin[row0]     * 50.0f;
    const float s1 = basin[row0 + 1] * 50.0f;
    const float* __restrict__ rl0 = runoff + (size_t)row0 * T_LEN + lane - 32;
    const float* __restrict__ rl1 = rl0 + T_LEN;
    float* __restrict__ ol0 = out + (size_t)row0 * T_LEN + lane;
    float* __restrict__ ol1 = ol0 + T_LEN;

    float Abuf[32], Bbuf[32], y;

    // ---- warm loads (group 0): t = chunk*256 + lane - 32; t<0 only for chunk 0 ----
#pragma unroll
    for (int c = 0; c < NSER; c++) {
        if ((c & 15) == 0) {
            T0[c][lane] = 0.0f;                       // lane-32 < 0 always
        } else {
            const float* gp = ((c < 16) ? rl0 : rl1) + (c & 15) * CHUNK;
            cpasync4(T0u + c * 132, gp);
        }
    }
    cpcommit();
    PREFETCH(T1u, 1);                                 // group 1 in flight
    cpwait<1>();                                      // warm batch done
    __syncwarp();

#pragma unroll
    for (int j = 0; j < 32; j++) Abuf[j] = T0[lane][j];
    // warm-start FIR: y = outlet at chunk-start - 1 (raw units; scaled at STG)
    {
        float s = 0.0f;
#pragma unroll
        for (int j = 12; j < 32; j++) s += Abuf[j];                 // lags 0..19
        float s2 = 0.0f;
#pragma unroll
        for (int j = 0; j < 12; j++) s2 = fmaf(GW[11 - j], Abuf[j], s2);  // 20..31
        y = s + s2;
    }
    __syncwarp();   // all lanes done reading T0 before it becomes a cp target

    // ---- 8 main groups of 32 steps, double-buffered, unroll 1 (I$-friendly) ----
#pragma unroll 1
    for (int gg = 0; gg < 4; gg++) {
        const int g1 = 2 * gg + 1;
        // --- group g1: inputs in T1; prefetch g1+1 -> T0 ---
        PREFETCH(T0u, g1 + 1);
        cpwait<1>();                                  // g1's batch done
        __syncwarp();
        GROUP_BODY(Abuf, Bbuf, T1);
        __syncwarp();
        DRAIN(T1, g1);
        __syncwarp();

        const int g2 = 2 * gg + 2;
        // --- group g2: inputs in T0; prefetch g2+1 -> T1 (except last) ---
        if (gg < 3) {
            PREFETCH(T1u, g2 + 1);
            cpwait<1>();
        } else {
            cpwait<0>();
        }
        __syncwarp();
        GROUP_BODY(Bbuf, Abuf, T0);
        __syncwarp();
        DRAIN(T0, g2);
        __syncwarp();
    }
}

extern "C" void kernel_launch(void* const* d_in, const int* in_sizes, int n_in,
                              void* d_out, int out_size)
{
    const float* runoff = (const float*)d_in[0];   // (B, T) float32
    const float* basin  = (const float*)d_in[1];   // (B, 1) float32
    float* out = (float*)d_out;                    // (B, T) float32

    int B = in_sizes[1];                           // 8192
    int rows_per_block = 2 * WPB;                  // 8
    int blocks = (B + rows_per_block - 1) / rows_per_block;   // 1024
    kinematic_wave_kernel<<<blocks, 32 * WPB>>>(runoff, basin, out, B);
}

// round 7
// speedup vs baseline: 1.0981x; 1.0981x over previous
#include <cuda_runtime.h>
#include <cuda_bf16.h>
#include <cstdint>

// KinematicWaveRouting via the scalar transfer function of the 20-segment chain.
//   y_t = y_{t-1} + u_t - sum_{m=20..31} c_m * u_{t-m},  u = runoff * basin * 50
//   c_m renormalized (sum = 1 exactly); max lag 31 -> full 32-reg prev window.
// One warp per row, lane = 128-step chunk, warm-started 32 steps early.
// Double-buffered smem transpose tile; next group's inputs prefetched with
// cp.async (single base pointer -> immediate-offset LDGSTS, minimal ALU),
// waited one full group later.  __launch_bounds__(128,6): 24 warps/SM.

#define T_LEN   4096
#define CHUNK   128
#define NCHUNK  32
#define RPB     4
#define NTAPS   12

// -c_m (renormalized), m = 20..31
static __device__ constexpr float CNEG[NTAPS] = {
    -0.12157942f, -0.24315882f, -0.25531676f, -0.18723229f,
    -0.10765857f, -0.05167612f, -0.02153171f, -0.00799749f,
    -0.00269915f, -0.00083973f, -0.00024352f, -0.00006643f
};
// g_m for m = 20..31 (warm-start FIR weights; g_m = 1 for m <= 19)
static __device__ constexpr float GW[12] = {
    0.878423345f, 0.635270036f, 0.379959062f, 0.192731014f,
    0.085074886f, 0.033399937f, 0.011868715f, 0.003871403f,
    0.001172310f, 0.000332598f, 0.000089080f, 0.000022666f
};

__device__ __forceinline__ void cpasync4(uint32_t s, const float* g) {
    asm volatile("cp.async.ca.shared.global [%0], [%1], 4;" :: "r"(s), "l"(g) : "memory");
}
__device__ __forceinline__ void cpcommit() {
    asm volatile("cp.async.commit_group;" ::: "memory");
}
template <int N>
__device__ __forceinline__ void cpwait() {
    asm volatile("cp.async.wait_group %0;" :: "n"(N) : "memory");
}

// Prefetch group GIDX's 32 inputs (coalesced 128B line per c) into the tile
// whose u32 base (already + lane*4) is TU. rl = rrow + lane - 32.
// Single base pointer: all offsets are compile-time immediates.
#define PREFETCH(TU, GIDX)                                                  \
    do {                                                                    \
        _Pragma("unroll")                                                   \
        for (int c = 0; c < NCHUNK; c++)                                    \
            cpasync4((TU) + c * 132, rl + c * CHUNK + (GIDX) * 32);         \
        cpcommit();                                                         \
    } while (0)

// One 32-step group: PREV[32]/CUR[32] register windows; outlet values
// overwrite the lane's own tile row in place.
#define GROUP_BODY(PREV, CUR, TC)                                           \
    do {                                                                    \
        float* tlrow = &TC[lane][0];                                        \
        _Pragma("unroll")                                                   \
        for (int j2 = 0; j2 < 32; j2++) CUR[j2] = tlrow[j2];                \
        _Pragma("unroll")                                                   \
        for (int m = 0; m < 32; m++) {                                      \
            float acc = CUR[m];                                             \
            _Pragma("unroll")                                               \
            for (int j = 0; j < NTAPS; j++) {                               \
                const int k = m - (20 + j);                                 \
                float w = (k >= 0) ? CUR[k] : PREV[32 + k];                 \
                acc = fmaf(CNEG[j], w, acc);                                \
            }                                                               \
            y += acc;                                                       \
            tlrow[m] = y;                                                   \
        }                                                                   \
    } while (0)

// Coalesced scaled store of group GIDX's outlets.
#define DRAIN(TC, GIDX)                                                     \
    do {                                                                    \
        _Pragma("unroll 8")                                                 \
        for (int c = 0; c < NCHUNK; c++)                                    \
            orow[c * CHUNK + ((GIDX) - 1) * 32 + lane] =                    \
                TC[c][lane] * scale;                                        \
    } while (0)

__global__ __launch_bounds__(128, 6)
void kinematic_wave_kernel(const float* __restrict__ runoff,
                           const float* __restrict__ basin,
                           float* __restrict__ out,
                           int B)
{
    __shared__ float tile[2][RPB][NCHUNK][33];   // stride 33: conflict-free

    const int warp = threadIdx.x >> 5;
    const int lane = threadIdx.x & 31;
    const int row  = blockIdx.x * RPB + warp;
    if (row >= B) return;

    float (*T0)[33] = tile[0][warp];
    float (*T1)[33] = tile[1][warp];
    const uint32_t T0u = (uint32_t)__cvta_generic_to_shared(&T0[0][0]) + lane * 4;
    const uint32_t T1u = (uint32_t)__cvta_generic_to_shared(&T1[0][0]) + lane * 4;

    const float scale = basin[row] * 50.0f;
    const float* __restrict__ rrow = runoff + (size_t)row * T_LEN;
    const float* __restrict__ rl   = rrow + lane - 32;     // prefetch base
    float*       __restrict__ orow = out + (size_t)row * T_LEN;

    float Abuf[32], Bbuf[32], y;

    // ---- warm loads (group 0): t = c*128 + lane - 32; OOB only at c==0 ----
    T0[0][lane] = 0.0f;
#pragma unroll
    for (int c = 1; c < NCHUNK; c++)
        cpasync4(T0u + c * 132, rl + c * CHUNK);
    cpcommit();
    PREFETCH(T1u, 1);                               // group 1 in flight
    cpwait<1>();                                    // warm batch landed
    __syncwarp();

#pragma unroll
    for (int j = 0; j < 32; j++) Abuf[j] = T0[lane][j];
    // warm-start FIR: y = outlet at chunk-start - 1 (raw units; scaled at STG)
    {
        float s = 0.0f;
#pragma unroll
        for (int j = 12; j < 32; j++) s += Abuf[j];                 // lags 0..19
        float s2 = 0.0f;
#pragma unroll
        for (int j = 0; j < 12; j++) s2 = fmaf(GW[11 - j], Abuf[j], s2);  // 20..31
        y = s + s2;
    }
    __syncwarp();   // all lanes done reading T0 before it becomes a cp target

    // ---- 4 pipelined groups of 32 steps ----
#pragma unroll 1
    for (int gg = 0; gg < 2; gg++) {
        const int g1 = 2 * gg + 1;
        // group g1: inputs in T1 (already landed); prefetch g1+1 -> T0
        PREFETCH(T0u, g1 + 1);
        cpwait<1>();                                // g1's batch (issued last group)
        __syncwarp();
        GROUP_BODY(Abuf, Bbuf, T1);
        __syncwarp();
        DRAIN(T1, g1);
        __syncwarp();

        const int g2 = 2 * gg + 2;
        // group g2: inputs in T0; prefetch g2+1 -> T1 (except after last)
        if (gg < 1) {
            PREFETCH(T1u, g2 + 1);
            cpwait<1>();
        } else {
            cpwait<0>();
        }
        __syncwarp();
        GROUP_BODY(Bbuf, Abuf, T0);
        __syncwarp();
        DRAIN(T0, g2);
        __syncwarp();
    }
}

extern "C" void kernel_launch(void* const* d_in, const int* in_sizes, int n_in,
                              void* d_out, int out_size)
{
    const float* runoff = (const float*)d_in[0];   // (B, T) float32
    const float* basin  = (const float*)d_in[1];   // (B, 1) float32
    float* out = (float*)d_out;                    // (B, T) float32

    int B = in_sizes[1];                           // 8192
    int blocks = (B + RPB - 1) / RPB;              // 2048
    kinematic_wave_kernel<<<blocks, 128>>>(runoff, basin, out, B);
}

// round 9
// speedup vs baseline: 1.3020x; 1.1856x over previous
#include <cuda_runtime.h>
#include <cuda_bf16.h>
#include <cstdint>

// KinematicWaveRouting via the scalar transfer function of the 20-segment chain.
//   y_t = y_{t-1} + u_t - sum_{j=0..9} c_j u_{t-20-j},   u = runoff * basin * 50
//   c = NegBinomial pmf truncated to 10 taps, then MOMENT-MATCHED:
//   renormalized (sum c = 1) and mean-corrected (sum m*c = 200/9 exactly).
// One warp per row, lane = 128-step chunk, warm-started 32 steps early.
// Tile stride = 36 floats (144B, 16B-aligned): CUR loads and DRAIN are
// LDS.128, prefetch is 16B cp.async, outputs written transposed into the
// just-consumed input buffer. All smem phases conflict-free.
// R8 bug fixed: orow no longer pre-offset by lane (DRAIN adds lane itself).

#define T_LEN    4096
#define CHUNK    128
#define NCHUNK   32
#define RPB      4
#define NTAPS    10
#define TSTRIDE  36          // floats per tile row (144 bytes)

// -c''_m, m = 20..29 (renormalized + mean-matched)
static __device__ constexpr float CNEG[NTAPS] = {
    -0.12131640f, -0.24323419f, -0.25539590f, -0.18729032f, -0.10769194f,
    -0.05169214f, -0.02153839f, -0.00799997f, -0.00269999f, -0.00114069f
};
// consistent warm-start weights g''_m = 1 - cumsum(c''), lags 20..28 (g29 = 0)
static __device__ constexpr float GW[9] = {
    0.87868360f, 0.63544941f, 0.38005352f, 0.19276319f, 0.08507126f,
    0.03337912f, 0.01184074f, 0.00384076f, 0.00114077f
};

__device__ __forceinline__ void cpasync16(uint32_t s, const float* g) {
    asm volatile("cp.async.cg.shared.global [%0], [%1], 16;" :: "r"(s), "l"(g) : "memory");
}
__device__ __forceinline__ void cpcommit() {
    asm volatile("cp.async.commit_group;" ::: "memory");
}
template <int N>
__device__ __forceinline__ void cpwait() {
    asm volatile("cp.async.wait_group %0;" :: "n"(N) : "memory");
}

// Prefetch group GIDX's inputs: 8 x 16B cp.async per lane. Instruction i
// covers chunks 4i..4i+3 (512B contiguous gmem per warp-instruction).
// rq = rrow + (lane>>3)*CHUNK + (lane&7)*4 - 32;  TU16 = tile base + lane slot.
#define PREFETCH16(TU16, GIDX)                                              \
    do {                                                                    \
        _Pragma("unroll")                                                   \
        for (int i = 0; i < 8; i++)                                         \
            cpasync16((TU16) + i * 576, rq + i * 512 + (GIDX) * 32);        \
        cpcommit();                                                         \
    } while (0)

// Load this group's 32 inputs for the lane's chunk: 8 x LDS.128 (conflict-free).
#define LOAD_CUR(CUR, TB)                                                   \
    do {                                                                    \
        const float4* r4 = (const float4*)((TB) + lane * TSTRIDE);          \
        _Pragma("unroll")                                                   \
        for (int k = 0; k < 8; k++) {                                       \
            float4 q = r4[k];                                               \
            CUR[4 * k] = q.x; CUR[4 * k + 1] = q.y;                         \
            CUR[4 * k + 2] = q.z; CUR[4 * k + 3] = q.w;                     \
        }                                                                   \
    } while (0)

// 32 steps; outputs written TRANSPOSED: step m, lane l -> TB[m*36 + l]
// (contiguous STS across the warp, conflict-free).
#define GROUP_BODY(PREV, CUR, TB)                                           \
    do {                                                                    \
        _Pragma("unroll")                                                   \
        for (int m = 0; m < 32; m++) {                                      \
            float acc = CUR[m];                                             \
            _Pragma("unroll")                                               \
            for (int j = 0; j < NTAPS; j++) {                               \
                const int k = m - (20 + j);                                 \
                float w = (k >= 0) ? CUR[k] : PREV[32 + k];                 \
                acc = fmaf(CNEG[j], w, acc);                                \
            }                                                               \
            y += acc;                                                       \
            (TB)[m * TSTRIDE + lane] = y;                                   \
        }                                                                   \
    } while (0)

// Drain group GIDX: lane reads step-row lane (chunks 0..31) as 8 x LDS.128,
// stores coalesced STG per chunk. Output time = c*CHUNK + (GIDX-1)*32 + lane.
#define DRAIN(TB, GIDX)                                                     \
    do {                                                                    \
        const float4* r4 = (const float4*)((TB) + lane * TSTRIDE);          \
        _Pragma("unroll")                                                   \
        for (int k = 0; k < 8; k++) {                                       \
            float4 v = r4[k];                                               \
            orow[(4 * k + 0) * CHUNK + ((GIDX) - 1) * 32 + lane] = v.x * scale; \
            orow[(4 * k + 1) * CHUNK + ((GIDX) - 1) * 32 + lane] = v.y * scale; \
            orow[(4 * k + 2) * CHUNK + ((GIDX) - 1) * 32 + lane] = v.z * scale; \
            orow[(4 * k + 3) * CHUNK + ((GIDX) - 1) * 32 + lane] = v.w * scale; \
        }                                                                   \
    } while (0)

__global__ __launch_bounds__(128, 6)
void kinematic_wave_kernel(const float* __restrict__ runoff,
                           const float* __restrict__ basin,
                           float* __restrict__ out,
                           int B)
{
    __shared__ __align__(16) float tile[2][RPB][NCHUNK * TSTRIDE];

    const int warp = threadIdx.x >> 5;
    const int lane = threadIdx.x & 31;
    const int row  = blockIdx.x * RPB + warp;
    if (row >= B) return;

    float* X = &tile[0][warp][0];
    float* Y = &tile[1][warp][0];
    const uint32_t lslot = (uint32_t)((lane >> 3) * 144 + (lane & 7) * 16);
    const uint32_t Xu16 = (uint32_t)__cvta_generic_to_shared(X) + lslot;
    const uint32_t Yu16 = (uint32_t)__cvta_generic_to_shared(Y) + lslot;

    const float scale = basin[row] * 50.0f;
    const float* __restrict__ rrow = runoff + (size_t)row * T_LEN;
    const float* __restrict__ rq   = rrow + (lane >> 3) * CHUNK + (lane & 7) * 4 - 32;
    float*       __restrict__ orow = out + (size_t)row * T_LEN;   // FIX: no +lane

    float W0[32], W1[32], y;

    // ---- warm inputs (group 0) -> X: chunk 0 is all t<0 (zeros) ----
    X[lane] = 0.0f;                                   // chunk-0 row, float = lane
#pragma unroll
    for (int i = 0; i < 8; i++) {
        if (i == 0) {
            if ((lane >> 3) != 0) cpasync16(Xu16, rq);
        } else {
            cpasync16(Xu16 + i * 576, rq + i * 512);
        }
    }
    cpcommit();
    PREFETCH16(Yu16, 1);                              // group 1 in flight
    cpwait<1>();                                      // warm batch landed
    __syncwarp();

    LOAD_CUR(W0, X);
    // warm FIR: W0[j] = u(t0-32+j), lag = 31-j; y = outlet at t0-1
    {
        float s = 0.0f;
#pragma unroll
        for (int j = 12; j < 32; j++) s += W0[j];                 // lags 0..19
        float s2 = 0.0f;
#pragma unroll
        for (int j = 3; j < 12; j++) s2 = fmaf(GW[11 - j], W0[j], s2); // lags 20..28
        y = s + s2;
    }
    __syncwarp();                                     // X free for prefetch

    // ---- group 1: inputs in Y; prefetch G2 -> X ----
    PREFETCH16(Xu16, 2);
    cpwait<1>(); __syncwarp();
    LOAD_CUR(W1, Y); __syncwarp();
    GROUP_BODY(W0, W1, Y); __syncwarp();
    DRAIN(Y, 1); __syncwarp();

    // ---- group 2: inputs in X; prefetch G3 -> Y ----
    PREFETCH16(Yu16, 3);
    cpwait<1>(); __syncwarp();
    LOAD_CUR(W0, X); __syncwarp();
    GROUP_BODY(W1, W0, X); __syncwarp();
    DRAIN(X, 2); __syncwarp();

    // ---- group 3: inputs in Y; prefetch G4 -> X ----
    PREFETCH16(Xu16, 4);
    cpwait<1>(); __syncwarp();
    LOAD_CUR(W1, Y); __syncwarp();
    GROUP_BODY(W0, W1, Y); __syncwarp();
    DRAIN(Y, 3); __syncwarp();

    // ---- group 4: inputs in X ----
    cpwait<0>(); __syncwarp();
    LOAD_CUR(W0, X); __syncwarp();
    GROUP_BODY(W1, W0, X); __syncwarp();
    DRAIN(X, 4);
}

extern "C" void kernel_launch(void* const* d_in, const int* in_sizes, int n_in,
                              void* d_out, int out_size)
{
    const float* runoff = (const float*)d_in[0];   // (B, T) float32
    const float* basin  = (const float*)d_in[1];   // (B, 1) float32
    float* out = (float*)d_out;                    // (B, T) float32

    int B = in_sizes[1];                           // 8192
    int blocks = (B + RPB - 1) / RPB;              // 2048
    kinematic_wave_kernel<<<blocks, 128>>>(runoff, basin, out, B);
}